// round 1
// baseline (speedup 1.0000x reference)
#include <cuda_runtime.h>
#include <cuda_bf16.h>

// FusionLoss: scalar loss over B=256 batches, K=16 keypoints.
// Inputs (metadata order):
//   d_in[0] output f32 [256,1,256,256]  (only 4096 gathered elements used)
//   d_in[1] mask   i32 [256,16]
//   d_in[2] ind    i32 [256,16]
//   d_in[3] target f32 [256,16,1]
//   d_in[4] gt_2d  f32 [256,32]
// Output: 1 float.

#define B   256
#define K   16
#define HW  65536
#define NE  12

static __constant__ int   c_ID1[NE] = {0, 1, 3, 4, 10, 11, 13, 14, 2, 3, 12, 13};
static __constant__ int   c_ID2[NE] = {1, 2, 4, 5, 11, 12, 14, 15, 6, 6, 8, 8};
static __constant__ int   c_GID[NE] = {0, 0, 0, 0, 1, 1, 1, 1, 2, 2, 3, 3};
static __constant__ float c_WGT[NE] = {
    1.0085885098415446f, 1.0f, 1.0f, 1.0085885098415446f,
    1.1375361376887123f, 1.0f, 1.0f, 1.1375361376887123f,
    1.0f, 1.0f, 1.0f, 1.0f};

__global__ __launch_bounds__(B, 1)
void fusion_loss_kernel(const float* __restrict__ output,
                        const int*   __restrict__ mask,
                        const int*   __restrict__ ind,
                        const float* __restrict__ target,
                        const float* __restrict__ gt2d,
                        float*       __restrict__ out)
{
    const int b = threadIdx.x;   // one thread per batch sample

    // ---- contiguous per-batch rows (vectorized 16B loads) ----
    int   idx[K];
    int   msk[K];
    float tgt[K];
    float xy[2 * K];

    {
        const int4* ip = reinterpret_cast<const int4*>(ind + b * K);
        const int4* mp = reinterpret_cast<const int4*>(mask + b * K);
        const float4* tp = reinterpret_cast<const float4*>(target + b * K);
        const float4* gp = reinterpret_cast<const float4*>(gt2d + b * 2 * K);
#pragma unroll
        for (int i = 0; i < K / 4; i++) {
            int4 iv = ip[i];
            idx[4 * i + 0] = iv.x; idx[4 * i + 1] = iv.y;
            idx[4 * i + 2] = iv.z; idx[4 * i + 3] = iv.w;
            int4 mv = mp[i];
            msk[4 * i + 0] = mv.x; msk[4 * i + 1] = mv.y;
            msk[4 * i + 2] = mv.z; msk[4 * i + 3] = mv.w;
            float4 tv = tp[i];
            tgt[4 * i + 0] = tv.x; tgt[4 * i + 1] = tv.y;
            tgt[4 * i + 2] = tv.z; tgt[4 * i + 3] = tv.w;
        }
#pragma unroll
        for (int i = 0; i < 2 * K / 4; i++) {
            float4 gv = gp[i];
            xy[4 * i + 0] = gv.x; xy[4 * i + 1] = gv.y;
            xy[4 * i + 2] = gv.z; xy[4 * i + 3] = gv.w;
        }
    }

    // ---- the gather: 16 independent LDGs per thread (MLP=16) ----
    float pred[K];
    const float* ob = output + (size_t)b * HW;   // channel dim is 1
#pragma unroll
    for (int k = 0; k < K; k++)
        pred[k] = __ldg(ob + idx[k]);

    // ---- smooth L1 (masked) ----
    float sl1 = 0.0f;
    int msum = 0;
#pragma unroll
    for (int k = 0; k < K; k++) {
        msum += msk[k];
        if (msk[k]) {
            float d  = pred[k] - tgt[k];
            float ad = fabsf(d);
            sl1 += (ad < 1.0f) ? 0.5f * ad * ad : (ad - 0.5f);
        }
    }

    // ---- 12-edge bone-length variance term ----
    float lE[NE];
    bool  vE[NE];
    float sum_g[4] = {0.f, 0.f, 0.f, 0.f};
    float num_g[4] = {0.f, 0.f, 0.f, 0.f};
#pragma unroll
    for (int e = 0; e < NE; e++) {
        int i1 = c_ID1[e], i2 = c_ID2[e];
        float dx = xy[2 * i1]     - xy[2 * i2];
        float dy = xy[2 * i1 + 1] - xy[2 * i2 + 1];
        float dz = pred[i1] - pred[i2];
        float le = sqrtf(dx * dx + dy * dy + dz * dz) * c_WGT[e];
        bool  v  = (tgt[i1] > 0.5f) && (tgt[i2] > 0.5f);
        lE[e] = le;
        vE[e] = v;
        if (v) { num_g[c_GID[e]] += 1.0f; sum_g[c_GID[e]] += le; }
    }
    float Eg[4], ng[4];
#pragma unroll
    for (int g = 0; g < 4; g++) {
        ng[g] = fmaxf(num_g[g], 1.0f);
        Eg[g] = (num_g[g] > 0.5f) ? (sum_g[g] / ng[g]) : 0.0f;
    }
    float per = 0.0f;
#pragma unroll
    for (int e = 0; e < NE; e++) {
        if (vE[e] && lE[e] > 0.0f) {
            int g = c_GID[e];
            float d = lE[e] - Eg[g];
            per += d * d / (2.0f * ng[g]);
        }
    }
    float var = (msum == 0) ? per : 0.0f;

    // ---- block reduction of (sl1, num, var) ----
    __shared__ float s_sl1[B];
    __shared__ float s_num[B];
    __shared__ float s_var[B];
    s_sl1[b] = sl1;
    s_num[b] = (float)msum;
    s_var[b] = var;
    __syncthreads();
#pragma unroll
    for (int s = B / 2; s > 0; s >>= 1) {
        if (b < s) {
            s_sl1[b] += s_sl1[b + s];
            s_num[b] += s_num[b + s];
            s_var[b] += s_var[b + s];
        }
        __syncthreads();
    }
    if (b == 0) {
        float reg = s_sl1[0] / (s_num[0] + 0.0001f);
        out[0] = reg + 0.01f * (s_var[0] * (1.0f / (float)B));
    }
}

extern "C" void kernel_launch(void* const* d_in, const int* in_sizes, int n_in,
                              void* d_out, int out_size)
{
    const float* output = (const float*)d_in[0];
    const int*   mask   = (const int*)d_in[1];
    const int*   ind    = (const int*)d_in[2];
    const float* target = (const float*)d_in[3];
    const float* gt2d   = (const float*)d_in[4];
    float*       out    = (float*)d_out;

    fusion_loss_kernel<<<1, B>>>(output, mask, ind, target, gt2d, out);
}

// round 2
// speedup vs baseline: 1.4987x; 1.4987x over previous
#include <cuda_runtime.h>
#include <cuda_bf16.h>

// FusionLoss: scalar loss over B=256 batches, K=16 keypoints.
// Inputs (metadata order):
//   d_in[0] output f32 [256,1,256,256]  (only 4096 gathered elements used)
//   d_in[1] mask   i32 [256,16]
//   d_in[2] ind    i32 [256,16]
//   d_in[3] target f32 [256,16,1]
//   d_in[4] gt_2d  f32 [256,32]
// Output: 1 float.
//
// Strategy: one 32-thread block per batch sample (256 blocks spread over
// 148 SMs) so the 4096 random gathers hit DRAM with full chip-level MLP
// instead of serializing through one SM's L1tex queue. Single kernel with
// threadfence+ticket last-block reduction (no second launch).

#define B   256
#define K   16
#define HW  65536
#define NE  12

static __constant__ int   c_ID1[NE] = {0, 1, 3, 4, 10, 11, 13, 14, 2, 3, 12, 13};
static __constant__ int   c_ID2[NE] = {1, 2, 4, 5, 11, 12, 14, 15, 6, 6, 8, 8};
static __constant__ int   c_GID[NE] = {0, 0, 0, 0, 1, 1, 1, 1, 2, 2, 3, 3};
static __constant__ float c_WGT[NE] = {
    1.0085885098415446f, 1.0f, 1.0f, 1.0085885098415446f,
    1.1375361376887123f, 1.0f, 1.0f, 1.1375361376887123f,
    1.0f, 1.0f, 1.0f, 1.0f};

// Scratch (device globals — no allocation allowed).
__device__ float        g_psl1[B];
__device__ float        g_pnum[B];
__device__ float        g_pvar[B];
__device__ unsigned int g_ticket = 0;   // reset by last block each call

__global__ __launch_bounds__(32, 8)
void fusion_loss_kernel(const float* __restrict__ output,
                        const int*   __restrict__ mask,
                        const int*   __restrict__ ind,
                        const float* __restrict__ target,
                        const float* __restrict__ gt2d,
                        float*       __restrict__ out)
{
    const int b    = blockIdx.x;     // one block per batch sample
    const int lane = threadIdx.x;    // 32 lanes
    const unsigned FULL = 0xffffffffu;

    // ---- per-k loads: lanes 0..15 own keypoint k = lane ----
    float pred = 0.0f, tg = 0.0f;
    int   mk = 0;
    if (lane < K) {
        int idx = __ldg(ind    + b * K + lane);
        mk      = __ldg(mask   + b * K + lane);
        tg      = __ldg(target + b * K + lane);
        pred    = __ldg(output + (size_t)b * HW + idx);   // the random gather
    }
    // lanes 0..31 each hold one xy scalar (gt_2d row has 32 floats)
    float xyv = __ldg(gt2d + b * 2 * K + lane);

    // ---- smooth L1 partial (per lane, masked) ----
    float sl1 = 0.0f;
    if (lane < K && mk) {
        float d  = pred - tg;
        float ad = fabsf(d);
        sl1 = (ad < 1.0f) ? 0.5f * ad * ad : (ad - 0.5f);
    }
    float msum = (lane < K) ? (float)mk : 0.0f;

    // ---- 12-edge bone-length term: lanes 0..11 own edge e = lane ----
    float le = 0.0f;
    float visf = 0.0f;
    int   gid = 0;
    {
        int e  = (lane < NE) ? lane : 0;
        int i1 = c_ID1[e], i2 = c_ID2[e];
        gid    = c_GID[e];
        float x1 = __shfl_sync(FULL, xyv, 2 * i1);
        float y1 = __shfl_sync(FULL, xyv, 2 * i1 + 1);
        float x2 = __shfl_sync(FULL, xyv, 2 * i2);
        float y2 = __shfl_sync(FULL, xyv, 2 * i2 + 1);
        float z1 = __shfl_sync(FULL, pred, i1);
        float z2 = __shfl_sync(FULL, pred, i2);
        float t1 = __shfl_sync(FULL, tg, i1);
        float t2 = __shfl_sync(FULL, tg, i2);
        if (lane < NE) {
            float dx = x1 - x2, dy = y1 - y2, dz = z1 - z2;
            le   = sqrtf(dx * dx + dy * dy + dz * dz) * c_WGT[lane];
            visf = ((t1 > 0.5f) && (t2 > 0.5f)) ? 1.0f : 0.0f;
        }
    }

    // group sums: every lane < NE rebuilds num_g/sum_g for its group by
    // shuffling all 12 (le, visf) pairs — 24 shuffles, trivial cost.
    float num_g = 0.0f, sum_g = 0.0f;
#pragma unroll
    for (int e = 0; e < NE; e++) {
        float lv = __shfl_sync(FULL, le,   e);
        float vv = __shfl_sync(FULL, visf, e);
        if (c_GID[e] == gid) { num_g += vv; sum_g += lv * vv; }
    }
    float term = 0.0f;
    if (lane < NE) {
        float ng = fmaxf(num_g, 1.0f);
        float Eg = (num_g > 0.5f) ? (sum_g / ng) : 0.0f;
        if (visf > 0.5f && le > 0.0f) {
            float d = le - Eg;
            term = d * d / (2.0f * ng);
        }
    }

    // ---- warp reductions ----
#pragma unroll
    for (int s = 16; s > 0; s >>= 1) {
        sl1  += __shfl_xor_sync(FULL, sl1,  s);
        msum += __shfl_xor_sync(FULL, msum, s);
        term += __shfl_xor_sync(FULL, term, s);
    }
    // var term only counts samples whose mask row sums to 0
    float var = (msum == 0.0f) ? term : 0.0f;

    // ---- publish partial, ticket, last block finalizes ----
    if (lane == 0) {
        g_psl1[b] = sl1;
        g_pnum[b] = msum;
        g_pvar[b] = var;
        __threadfence();
    }
    __syncwarp(FULL);

    unsigned ticket = 0;
    if (lane == 0)
        ticket = atomicAdd(&g_ticket, 1u);
    ticket = __shfl_sync(FULL, ticket, 0);

    if (ticket == (unsigned)(gridDim.x - 1)) {
        // last block: sum 256 partials (fixed order per lane -> deterministic)
        __threadfence();
        float a = 0.0f, n = 0.0f, v = 0.0f;
        const volatile float* p1 = g_psl1;
        const volatile float* p2 = g_pnum;
        const volatile float* p3 = g_pvar;
        for (int i = lane; i < B; i += 32) {
            a += p1[i];
            n += p2[i];
            v += p3[i];
        }
#pragma unroll
        for (int s = 16; s > 0; s >>= 1) {
            a += __shfl_xor_sync(FULL, a, s);
            n += __shfl_xor_sync(FULL, n, s);
            v += __shfl_xor_sync(FULL, v, s);
        }
        if (lane == 0) {
            float reg = a / (n + 0.0001f);
            out[0] = reg + 0.01f * (v * (1.0f / (float)B));
            g_ticket = 0;            // reset for next graph replay
            __threadfence();
        }
    }
}

extern "C" void kernel_launch(void* const* d_in, const int* in_sizes, int n_in,
                              void* d_out, int out_size)
{
    const float* output = (const float*)d_in[0];
    const int*   mask   = (const int*)d_in[1];
    const int*   ind    = (const int*)d_in[2];
    const float* target = (const float*)d_in[3];
    const float* gt2d   = (const float*)d_in[4];
    float*       out    = (float*)d_out;

    fusion_loss_kernel<<<B, 32>>>(output, mask, ind, target, gt2d, out);
}

// round 3
// speedup vs baseline: 2.1213x; 1.4154x over previous
#include <cuda_runtime.h>
#include <cuda_bf16.h>

// FusionLoss: scalar loss over B=256 batches, K=16 keypoints.
// Inputs (metadata order):
//   d_in[0] output f32 [256,1,256,256]  (only 4096 gathered elements used)
//   d_in[1] mask   i32 [256,16]
//   d_in[2] ind    i32 [256,16]
//   d_in[3] target f32 [256,16,1]
//   d_in[4] gt_2d  f32 [256,32]
// Output: 1 float.
//
// One 32-thread block per sample (full-chip MLP for the random gathers).
// Cross-block combine via 3 global float atomic accumulators (single-address
// REDG path) + ticket; last finisher reads 3 values, finalizes, re-zeros.

#define B   256
#define K   16
#define HW  65536
#define NE  12

static __constant__ int   c_ID1[NE] = {0, 1, 3, 4, 10, 11, 13, 14, 2, 3, 12, 13};
static __constant__ int   c_ID2[NE] = {1, 2, 4, 5, 11, 12, 14, 15, 6, 6, 8, 8};
static __constant__ int   c_GID[NE] = {0, 0, 0, 0, 1, 1, 1, 1, 2, 2, 3, 3};
static __constant__ float c_WGT[NE] = {
    1.0085885098415446f, 1.0f, 1.0f, 1.0085885098415446f,
    1.1375361376887123f, 1.0f, 1.0f, 1.1375361376887123f,
    1.0f, 1.0f, 1.0f, 1.0f};

// Scratch (device globals — no allocation allowed). Zero-initialized at load;
// the last block re-zeros them each call so graph replays are identical.
__device__ float        g_acc_sl1 = 0.0f;
__device__ float        g_acc_num = 0.0f;
__device__ float        g_acc_var = 0.0f;
__device__ unsigned int g_ticket  = 0;

__global__ __launch_bounds__(32, 8)
void fusion_loss_kernel(const float* __restrict__ output,
                        const int*   __restrict__ mask,
                        const int*   __restrict__ ind,
                        const float* __restrict__ target,
                        const float* __restrict__ gt2d,
                        float*       __restrict__ out)
{
    const int b    = blockIdx.x;     // one block per batch sample
    const int lane = threadIdx.x;    // 32 lanes
    const unsigned FULL = 0xffffffffu;

    // ---- per-k loads: lanes 0..15 own keypoint k = lane ----
    float pred = 0.0f, tg = 0.0f;
    int   mk = 0;
    if (lane < K) {
        int idx = __ldg(ind    + b * K + lane);
        mk      = __ldg(mask   + b * K + lane);
        tg      = __ldg(target + b * K + lane);
        pred    = __ldg(output + (size_t)b * HW + idx);   // the random gather
    }
    // lanes 0..31 each hold one xy scalar (gt_2d row has 32 floats)
    float xyv = __ldg(gt2d + b * 2 * K + lane);

    // ---- smooth L1 partial (per lane, masked) ----
    float sl1 = 0.0f;
    if (lane < K && mk) {
        float d  = pred - tg;
        float ad = fabsf(d);
        sl1 = (ad < 1.0f) ? 0.5f * ad * ad : (ad - 0.5f);
    }
    float msum = (lane < K) ? (float)mk : 0.0f;

    // ---- 12-edge bone-length term: lanes 0..11 own edge e = lane ----
    float le = 0.0f;
    float visf = 0.0f;
    int   gid = 0;
    {
        int e  = (lane < NE) ? lane : 0;
        int i1 = c_ID1[e], i2 = c_ID2[e];
        gid    = c_GID[e];
        float x1 = __shfl_sync(FULL, xyv, 2 * i1);
        float y1 = __shfl_sync(FULL, xyv, 2 * i1 + 1);
        float x2 = __shfl_sync(FULL, xyv, 2 * i2);
        float y2 = __shfl_sync(FULL, xyv, 2 * i2 + 1);
        float z1 = __shfl_sync(FULL, pred, i1);
        float z2 = __shfl_sync(FULL, pred, i2);
        float t1 = __shfl_sync(FULL, tg, i1);
        float t2 = __shfl_sync(FULL, tg, i2);
        if (lane < NE) {
            float dx = x1 - x2, dy = y1 - y2, dz = z1 - z2;
            le   = sqrtf(dx * dx + dy * dy + dz * dz) * c_WGT[lane];
            visf = ((t1 > 0.5f) && (t2 > 0.5f)) ? 1.0f : 0.0f;
        }
    }

    // group sums via 24 shuffles (lanes < NE rebuild their group's stats)
    float num_g = 0.0f, sum_g = 0.0f;
#pragma unroll
    for (int e = 0; e < NE; e++) {
        float lv = __shfl_sync(FULL, le,   e);
        float vv = __shfl_sync(FULL, visf, e);
        if (c_GID[e] == gid) { num_g += vv; sum_g += lv * vv; }
    }
    float term = 0.0f;
    if (lane < NE) {
        float ng = fmaxf(num_g, 1.0f);
        float Eg = (num_g > 0.5f) ? (sum_g / ng) : 0.0f;
        if (visf > 0.5f && le > 0.0f) {
            float d = le - Eg;
            term = d * d / (2.0f * ng);
        }
    }

    // ---- warp reductions ----
#pragma unroll
    for (int s = 16; s > 0; s >>= 1) {
        sl1  += __shfl_xor_sync(FULL, sl1,  s);
        msum += __shfl_xor_sync(FULL, msum, s);
        term += __shfl_xor_sync(FULL, term, s);
    }
    float var = (msum == 0.0f) ? term : 0.0f;

    // ---- accumulate via global atomics, then ticket ----
    unsigned ticket = 0;
    if (lane == 0) {
        atomicAdd(&g_acc_sl1, sl1);
        atomicAdd(&g_acc_num, msum);
        atomicAdd(&g_acc_var, var);
        __threadfence();                       // accs visible before ticket
        ticket = atomicAdd(&g_ticket, 1u);
    }
    ticket = __shfl_sync(FULL, ticket, 0);

    if (ticket == (unsigned)(B - 1) && lane == 0) {
        __threadfence();
        float a = *((volatile float*)&g_acc_sl1);
        float n = *((volatile float*)&g_acc_num);
        float v = *((volatile float*)&g_acc_var);
        float reg = a / (n + 0.0001f);
        out[0] = reg + 0.01f * (v * (1.0f / (float)B));
        // reset for the next graph replay
        *((volatile float*)&g_acc_sl1) = 0.0f;
        *((volatile float*)&g_acc_num) = 0.0f;
        *((volatile float*)&g_acc_var) = 0.0f;
        *((volatile unsigned int*)&g_ticket) = 0u;
        __threadfence();
    }
}

extern "C" void kernel_launch(void* const* d_in, const int* in_sizes, int n_in,
                              void* d_out, int out_size)
{
    const float* output = (const float*)d_in[0];
    const int*   mask   = (const int*)d_in[1];
    const int*   ind    = (const int*)d_in[2];
    const float* target = (const float*)d_in[3];
    const float* gt2d   = (const float*)d_in[4];
    float*       out    = (float*)d_out;

    fusion_loss_kernel<<<B, 32>>>(output, mask, ind, target, gt2d, out);
}

// round 4
// speedup vs baseline: 2.6713x; 1.2593x over previous
#include <cuda_runtime.h>
#include <cuda_bf16.h>

// FusionLoss: scalar loss over B=256 batches, K=16 keypoints.
// Inputs (metadata order):
//   d_in[0] output f32 [256,1,256,256]  (only 4096 gathered elements used)
//   d_in[1] mask   i32 [256,16]
//   d_in[2] ind    i32 [256,16]
//   d_in[3] target f32 [256,16,1]
//   d_in[4] gt_2d  f32 [256,32]
// Output: 1 float.
//
// 64 blocks x 128 threads; warp w of block b owns sample 4b+w.
// Gathers spread chip-wide (full MLP). Cross-block combine: relaxed float
// REDGs + acq_rel ticket (no MEMBAR); last finisher reads 3 accs, writes
// the scalar, re-zeros state for the next graph replay.

#define B    256
#define K    16
#define HW   65536
#define NE   12
#define WPB  4                      // warps (samples) per block
#define NBLK (B / WPB)              // 64

static __constant__ int   c_ID1[NE] = {0, 1, 3, 4, 10, 11, 13, 14, 2, 3, 12, 13};
static __constant__ int   c_ID2[NE] = {1, 2, 4, 5, 11, 12, 14, 15, 6, 6, 8, 8};
static __constant__ float c_WGT[NE] = {
    1.0085885098415446f, 1.0f, 1.0f, 1.0085885098415446f,
    1.1375361376887123f, 1.0f, 1.0f, 1.1375361376887123f,
    1.0f, 1.0f, 1.0f, 1.0f};

// Device-global scratch (no allocation allowed). Zero at load; the finisher
// re-zeros each call so graph replays see identical state.
__device__ float        g_acc_sl1 = 0.0f;
__device__ float        g_acc_num = 0.0f;
__device__ float        g_acc_var = 0.0f;
__device__ unsigned int g_ticket  = 0;

__global__ __launch_bounds__(128, 8)
void fusion_loss_kernel(const float* __restrict__ output,
                        const int*   __restrict__ mask,
                        const int*   __restrict__ ind,
                        const float* __restrict__ target,
                        const float* __restrict__ gt2d,
                        float*       __restrict__ out)
{
    const int warp = threadIdx.x >> 5;
    const int lane = threadIdx.x & 31;
    const int b    = blockIdx.x * WPB + warp;   // sample owned by this warp
    const unsigned FULL = 0xffffffffu;

    // ---- per-keypoint loads: lanes 0..15 own keypoint k = lane ----
    float pred = 0.0f, tg = 0.0f;
    float mk = 0.0f;
    if (lane < K) {
        int idx = __ldg(ind    + b * K + lane);
        mk      = (float)__ldg(mask + b * K + lane);
        tg      = __ldg(target + b * K + lane);
        pred    = __ldg(output + (size_t)b * HW + idx);   // random gather
    }
    float xyv = __ldg(gt2d + b * 2 * K + lane);           // all 32 lanes

    // ---- smooth L1 partial ----
    float sl1 = 0.0f;
    if (lane < K && mk != 0.0f) {
        float d  = pred - tg;
        float ad = fabsf(d);
        sl1 = (ad < 1.0f) ? 0.5f * ad * ad : (ad - 0.5f);
    }
    float msum = mk;   // zero for lanes >= K

    // ---- 12-edge bone term: lanes 0..11 own edge e = lane ----
    // Edge->group mapping is lane-contiguous: g0={0..3} g1={4..7} g2={8,9} g3={10,11}
    float le = 0.0f, visf = 0.0f;
    {
        int e  = (lane < NE) ? lane : 0;
        int i1 = c_ID1[e], i2 = c_ID2[e];
        float x1 = __shfl_sync(FULL, xyv, 2 * i1);
        float y1 = __shfl_sync(FULL, xyv, 2 * i1 + 1);
        float x2 = __shfl_sync(FULL, xyv, 2 * i2);
        float y2 = __shfl_sync(FULL, xyv, 2 * i2 + 1);
        float z1 = __shfl_sync(FULL, pred, i1);
        float z2 = __shfl_sync(FULL, pred, i2);
        float t1 = __shfl_sync(FULL, tg, i1);
        float t2 = __shfl_sync(FULL, tg, i2);
        if (lane < NE) {
            float dx = x1 - x2, dy = y1 - y2, dz = z1 - z2;
            le   = sqrtf(dx * dx + dy * dy + dz * dz) * c_WGT[lane];
            visf = ((t1 > 0.5f) && (t2 > 0.5f)) ? 1.0f : 0.0f;
        }
    }

    // ---- segmented butterfly for group sums (4 shuffles total) ----
    float sum_g = le * visf;
    float num_g = visf;
    {
        float s1 = __shfl_xor_sync(FULL, sum_g, 1);
        float n1 = __shfl_xor_sync(FULL, num_g, 1);
        sum_g += s1; num_g += n1;                 // pairs within each group
        float s2 = __shfl_xor_sync(FULL, sum_g, 2);
        float n2 = __shfl_xor_sync(FULL, num_g, 2);
        if (lane < 8) { sum_g += s2; num_g += n2; }  // 4-wide groups only
    }

    float term = 0.0f;
    if (lane < NE) {
        float ng = fmaxf(num_g, 1.0f);
        float Eg = (num_g > 0.5f) ? (sum_g / ng) : 0.0f;
        if (visf > 0.5f && le > 0.0f) {
            float d = le - Eg;
            term = d * d / (2.0f * ng);
        }
    }

    // ---- warp reductions: contributions only in lanes 0..15 -> 4 rounds,
    //      lane 0 ends with the full sum ----
#pragma unroll
    for (int s = 8; s > 0; s >>= 1) {
        sl1  += __shfl_xor_sync(FULL, sl1,  s);
        msum += __shfl_xor_sync(FULL, msum, s);
        term += __shfl_xor_sync(FULL, term, s);
    }
    float var = (msum == 0.0f) ? term : 0.0f;   // lane 0 value is the valid one

    // ---- block combine (4 warps) in shared memory ----
    __shared__ float s_part[WPB][3];
    if (lane == 0) {
        s_part[warp][0] = sl1;
        s_part[warp][1] = msum;
        s_part[warp][2] = var;
    }
    __syncthreads();

    if (threadIdx.x == 0) {
        float a = 0.0f, n = 0.0f, v = 0.0f;
#pragma unroll
        for (int w = 0; w < WPB; w++) {
            a += s_part[w][0];
            n += s_part[w][1];
            v += s_part[w][2];
        }
        // relaxed accumulator adds (REDG, fire-and-forget)
        atomicAdd(&g_acc_sl1, a);
        atomicAdd(&g_acc_num, n);
        atomicAdd(&g_acc_var, v);
        // acq_rel ticket: release makes our REDGs visible; acquire lets the
        // last finisher see everyone else's.
        unsigned ticket;
        asm volatile("atom.add.acq_rel.gpu.global.u32 %0, [%1], %2;"
                     : "=r"(ticket)
                     : "l"(&g_ticket), "r"(1u)
                     : "memory");
        if (ticket == (unsigned)(NBLK - 1)) {
            float sa = *((volatile float*)&g_acc_sl1);
            float sn = *((volatile float*)&g_acc_num);
            float sv = *((volatile float*)&g_acc_var);
            float reg = sa / (sn + 0.0001f);
            out[0] = reg + 0.01f * (sv * (1.0f / (float)B));
            // reset for next graph replay (kernel boundary orders these)
            *((volatile float*)&g_acc_sl1) = 0.0f;
            *((volatile float*)&g_acc_num) = 0.0f;
            *((volatile float*)&g_acc_var) = 0.0f;
            *((volatile unsigned int*)&g_ticket) = 0u;
        }
    }
}

extern "C" void kernel_launch(void* const* d_in, const int* in_sizes, int n_in,
                              void* d_out, int out_size)
{
    const float* output = (const float*)d_in[0];
    const int*   mask   = (const int*)d_in[1];
    const int*   ind    = (const int*)d_in[2];
    const float* target = (const float*)d_in[3];
    const float* gt2d   = (const float*)d_in[4];
    float*       out    = (float*)d_out;

    fusion_loss_kernel<<<NBLK, 32 * WPB>>>(output, mask, ind, target, gt2d, out);
}